// round 13
// baseline (speedup 1.0000x reference)
#include <cuda_runtime.h>
#include <cuda_bf16.h>
#include <cstdint>

#define NB 32
#define IJ 1024
#define ND 128
#define NK 64
#define CHUNKS 8
#define ROWS 128

#define FSTRB 272      // byte stride, f/c bf16 tiles (136 bf16, conflict-free)
#define SSTRB 144      // byte stride, sim bf16 tiles (72 bf16)

// smem layout (bytes)
#define OFF_FHI 0
#define OFF_FLO 34816
#define OFF_CHI 69632                 // c tiles; sim aliases this region after phase A
#define OFF_CLO 87040
#define OFF_SHI 69632                 // sim hi [128][72] bf16
#define OFF_SLO 88064
#define OFF_F2  106496
#define OFF_C2  107008
#define SMEM_TOTAL 107264

#define NBLK2 512                     // stage2 grid size (must match launch)

// ---------------- scratch ----------------
__device__ float g_psum[NB * CHUNKS * NK * ND];   // 8 MB
__device__ float g_ssum[NB * CHUNKS * NK];
__device__ float g_sq;
__device__ unsigned g_cnt;

// ---------------- helpers ----------------
__device__ __forceinline__ uint32_t smem_u32(const void* p) {
    uint32_t a;
    asm("{ .reg .u64 t; cvta.to.shared.u64 t, %1; cvt.u32.u64 %0, t; }" : "=r"(a) : "l"(p));
    return a;
}
__device__ __forceinline__ unsigned pack_bf2(float a, float b) {
    __nv_bfloat16 ha = __float2bfloat16(a), hb = __float2bfloat16(b);
    unsigned short ua = *reinterpret_cast<unsigned short*>(&ha);
    unsigned short ub = *reinterpret_cast<unsigned short*>(&hb);
    return (unsigned)ua | ((unsigned)ub << 16);
}
__device__ __forceinline__ void split2(float a, float b, uint32_t& hi, uint32_t& lo) {
    __nv_bfloat16 ha = __float2bfloat16(a), hb = __float2bfloat16(b);
    float fa = __bfloat162float(ha), fb = __bfloat162float(hb);
    hi = pack_bf2(a, b);
    lo = pack_bf2(a - fa, b - fb);
}
__device__ __forceinline__ void ldsm_x4(uint32_t* r, uint32_t addr) {
    asm volatile("ldmatrix.sync.aligned.m8n8.x4.shared.b16 {%0,%1,%2,%3}, [%4];"
                 : "=r"(r[0]), "=r"(r[1]), "=r"(r[2]), "=r"(r[3]) : "r"(addr));
}
__device__ __forceinline__ void ldsm_x4_t(uint32_t* r, uint32_t addr) {
    asm volatile("ldmatrix.sync.aligned.m8n8.x4.trans.shared.b16 {%0,%1,%2,%3}, [%4];"
                 : "=r"(r[0]), "=r"(r[1]), "=r"(r[2]), "=r"(r[3]) : "r"(addr));
}
__device__ __forceinline__ void ldsm_x2(uint32_t* r, uint32_t addr) {
    asm volatile("ldmatrix.sync.aligned.m8n8.x2.shared.b16 {%0,%1}, [%2];"
                 : "=r"(r[0]), "=r"(r[1]) : "r"(addr));
}
__device__ __forceinline__ void ldsm_x2_t(uint32_t* r, uint32_t addr) {
    asm volatile("ldmatrix.sync.aligned.m8n8.x2.trans.shared.b16 {%0,%1}, [%2];"
                 : "=r"(r[0]), "=r"(r[1]) : "r"(addr));
}
__device__ __forceinline__ void mma_bf16(float* d, const uint32_t* a, const uint32_t* b) {
    asm volatile("mma.sync.aligned.m16n8k16.row.col.f32.bf16.bf16.f32 "
                 "{%0,%1,%2,%3}, {%4,%5,%6,%7}, {%8,%9}, {%0,%1,%2,%3};"
                 : "+f"(d[0]), "+f"(d[1]), "+f"(d[2]), "+f"(d[3])
                 : "r"(a[0]), "r"(a[1]), "r"(a[2]), "r"(a[3]), "r"(b[0]), "r"(b[1]));
}

// ---------------- stage 1 ----------------
__global__ __launch_bounds__(256, 2)
void nv_stage1(const float* __restrict__ feat, const float* __restrict__ cent) {
    extern __shared__ char smem[];
    const uint32_t sb = smem_u32(smem);
    float* f2 = reinterpret_cast<float*>(smem + OFF_F2);
    float* c2 = reinterpret_cast<float*>(smem + OFF_C2);

    const int b     = blockIdx.y;
    const int chunk = blockIdx.x;
    const int tid   = threadIdx.x;
    const int wid   = tid >> 5;
    const int lane  = tid & 31;

    if (blockIdx.x == 0 && blockIdx.y == 0 && tid == 0) { g_sq = 0.f; g_cnt = 0u; }

    const float* cb = cent + (size_t)b * NK * ND;
    const float* fb = feat + (size_t)b * IJ * ND + (size_t)chunk * ROWS * ND;

    // ---- load f: 128 rows; split to bf16 hi/lo; f2 ----
    #pragma unroll
    for (int p = 0; p < 16; p++) {
        int r = wid + 8 * p;
        float4 v = *reinterpret_cast<const float4*>(&fb[r * ND + lane * 4]);
        uint32_t h0, l0, h1, l1;
        split2(v.x, v.y, h0, l0);
        split2(v.z, v.w, h1, l1);
        *reinterpret_cast<uint2*>(smem + OFF_FHI + r * FSTRB + lane * 8) = make_uint2(h0, h1);
        *reinterpret_cast<uint2*>(smem + OFF_FLO + r * FSTRB + lane * 8) = make_uint2(l0, l1);
        float s = v.x * v.x + v.y * v.y + v.z * v.z + v.w * v.w;
        #pragma unroll
        for (int o = 16; o; o >>= 1) s += __shfl_xor_sync(0xffffffffu, s, o);
        if (lane == 0) f2[r] = s;
    }
    // ---- load c: 64 rows ----
    #pragma unroll
    for (int p = 0; p < 8; p++) {
        int k = wid + 8 * p;
        float4 v = *reinterpret_cast<const float4*>(&cb[k * ND + lane * 4]);
        uint32_t h0, l0, h1, l1;
        split2(v.x, v.y, h0, l0);
        split2(v.z, v.w, h1, l1);
        *reinterpret_cast<uint2*>(smem + OFF_CHI + k * FSTRB + lane * 8) = make_uint2(h0, h1);
        *reinterpret_cast<uint2*>(smem + OFF_CLO + k * FSTRB + lane * 8) = make_uint2(l0, l1);
        float s = v.x * v.x + v.y * v.y + v.z * v.z + v.w * v.w;
        #pragma unroll
        for (int o = 16; o; o >>= 1) s += __shfl_xor_sync(0xffffffffu, s, o);
        if (lane == 0) c2[k] = s;
    }
    __syncthreads();

    // ================= phase A: fc = f . c^T  (HMMA bf16x3) =================
    const int r0 = wid * 16;
    float acc[8][4];
    #pragma unroll
    for (int nt = 0; nt < 8; nt++)
        #pragma unroll
        for (int j = 0; j < 4; j++) acc[nt][j] = 0.f;

    {
        uint32_t a_row = (uint32_t)(r0 + ((lane >> 3) & 1) * 8 + (lane & 7));
        uint32_t a_off = a_row * FSTRB + ((uint32_t)(lane >> 4)) * 16;
        uint32_t ah_addr = sb + OFF_FHI + a_off;
        uint32_t al_addr = sb + OFF_FLO + a_off;
        int l = lane & 15;
        uint32_t b_off0 = (uint32_t)(l & 7) * FSTRB + ((uint32_t)(l >> 3)) * 16;

        #pragma unroll
        for (int kk = 0; kk < 8; kk++) {
            uint32_t ko = kk * 32;             // 16 bf16 = 32 bytes
            uint32_t ah[4], al[4];
            ldsm_x4(ah, ah_addr + ko);
            ldsm_x4(al, al_addr + ko);
            #pragma unroll
            for (int nt = 0; nt < 8; nt++) {
                uint32_t bo = sb + OFF_CHI + b_off0 + (uint32_t)(nt * 8) * FSTRB + ko;
                uint32_t bh[2], bl[2];
                ldsm_x2(bh, bo);
                ldsm_x2(bl, bo + (OFF_CLO - OFF_CHI));
                mma_bf16(acc[nt], ah, bh);
                mma_bf16(acc[nt], ah, bl);
                mma_bf16(acc[nt], al, bh);
            }
        }
    }
    __syncthreads();   // all warps done reading c tiles; sim may alias them

    // ================= softmax (row in a 4-lane group) =================
    {
        const int q  = lane & 3;
        const int ra = r0 + (lane >> 2);
        const int rb = ra + 8;
        const float f2a = f2[ra], f2b = f2[rb];

        float mxa = -1e30f, mxb = -1e30f;
        #pragma unroll
        for (int nt = 0; nt < 8; nt++) {
            float c2x = c2[nt * 8 + 2 * q];
            float c2y = c2[nt * 8 + 2 * q + 1];
            acc[nt][0] = 2.f * acc[nt][0] - f2a - c2x;
            acc[nt][1] = 2.f * acc[nt][1] - f2a - c2y;
            acc[nt][2] = 2.f * acc[nt][2] - f2b - c2x;
            acc[nt][3] = 2.f * acc[nt][3] - f2b - c2y;
            mxa = fmaxf(mxa, fmaxf(acc[nt][0], acc[nt][1]));
            mxb = fmaxf(mxb, fmaxf(acc[nt][2], acc[nt][3]));
        }
        #pragma unroll
        for (int o = 1; o <= 2; o <<= 1) {
            mxa = fmaxf(mxa, __shfl_xor_sync(0xffffffffu, mxa, o));
            mxb = fmaxf(mxb, __shfl_xor_sync(0xffffffffu, mxb, o));
        }
        float sa = 0.f, sbm = 0.f;
        #pragma unroll
        for (int nt = 0; nt < 8; nt++) {
            acc[nt][0] = __expf(acc[nt][0] - mxa);
            acc[nt][1] = __expf(acc[nt][1] - mxa);
            acc[nt][2] = __expf(acc[nt][2] - mxb);
            acc[nt][3] = __expf(acc[nt][3] - mxb);
            sa  += acc[nt][0] + acc[nt][1];
            sbm += acc[nt][2] + acc[nt][3];
        }
        #pragma unroll
        for (int o = 1; o <= 2; o <<= 1) {
            sa  += __shfl_xor_sync(0xffffffffu, sa, o);
            sbm += __shfl_xor_sync(0xffffffffu, sbm, o);
        }
        const float inva = 1.f / sa, invb = 1.f / sbm;

        #pragma unroll
        for (int nt = 0; nt < 8; nt++) {
            float s0 = acc[nt][0] * inva, s1 = acc[nt][1] * inva;
            float s2 = acc[nt][2] * invb, s3 = acc[nt][3] * invb;
            uint32_t h0, l0, h1, l1;
            split2(s0, s1, h0, l0);
            split2(s2, s3, h1, l1);
            uint32_t co = (uint32_t)(nt * 16 + q * 4);
            *reinterpret_cast<uint32_t*>(smem + OFF_SHI + ra * SSTRB + co) = h0;
            *reinterpret_cast<uint32_t*>(smem + OFF_SLO + ra * SSTRB + co) = l0;
            *reinterpret_cast<uint32_t*>(smem + OFF_SHI + rb * SSTRB + co) = h1;
            *reinterpret_cast<uint32_t*>(smem + OFF_SLO + rb * SSTRB + co) = l1;
        }
    }
    __syncthreads();

    // ---- ssum[k] = sum_r (sim_hi + sim_lo)  (threads 0..63, smem column sums) ----
    if (tid < 64) {
        const uint16_t* ph = reinterpret_cast<const uint16_t*>(smem + OFF_SHI) + tid;
        const uint16_t* pl = reinterpret_cast<const uint16_t*>(smem + OFF_SLO) + tid;
        float s = 0.f;
        #pragma unroll 8
        for (int r = 0; r < ROWS; r++) {
            s += __uint_as_float((uint32_t)ph[r * (SSTRB / 2)] << 16);
            s += __uint_as_float((uint32_t)pl[r * (SSTRB / 2)] << 16);
        }
        g_ssum[(b * CHUNKS + chunk) * NK + tid] = s;
    }

    // ================= phase B: psum = sim^T . f  (HMMA bf16x3) =================
    {
        const int mt = wid & 3;          // k-tile (16 k)
        const int dh = wid >> 2;         // d-half (64 d)
        float bcc[8][4];
        #pragma unroll
        for (int nt = 0; nt < 8; nt++)
            #pragma unroll
            for (int j = 0; j < 4; j++) bcc[nt][j] = 0.f;

        uint32_t mi = (uint32_t)(lane >> 3);
        uint32_t sa_off = ((mi >> 1) * 8 + (uint32_t)(lane & 7)) * SSTRB
                        + ((uint32_t)(mt * 16) + (mi & 1) * 8) * 2;
        uint32_t fb_row = (((uint32_t)(lane & 15) >> 3) * 8 + (uint32_t)(lane & 7));

        #pragma unroll
        for (int rr = 0; rr < 8; rr++) {
            uint32_t sh[4], sl[4];
            uint32_t sa_addr = sb + OFF_SHI + (uint32_t)(rr * 16) * SSTRB + sa_off;
            ldsm_x4_t(sh, sa_addr);
            ldsm_x4_t(sl, sa_addr + (OFF_SLO - OFF_SHI));
            uint32_t fbase = (uint32_t)(rr * 16) * FSTRB + fb_row * FSTRB;
            #pragma unroll
            for (int nt = 0; nt < 8; nt++) {
                uint32_t n0 = (uint32_t)(dh * 64 + nt * 8);
                uint32_t fh[2], fl[2];
                ldsm_x2_t(fh, sb + OFF_FHI + fbase + n0 * 2);
                ldsm_x2_t(fl, sb + OFF_FLO + fbase + n0 * 2);
                mma_bf16(bcc[nt], sh, fh);
                mma_bf16(bcc[nt], sh, fl);
                mma_bf16(bcc[nt], sl, fh);
            }
        }

        // epilogue: write fragments to g_psum
        const size_t base = ((size_t)(b * CHUNKS + chunk) * NK) * ND;
        const int ka  = mt * 16 + (lane >> 2);
        const int kb2 = ka + 8;
        const int dd  = dh * 64 + 2 * (lane & 3);
        #pragma unroll
        for (int nt = 0; nt < 8; nt++) {
            *reinterpret_cast<float2*>(&g_psum[base + (size_t)ka * ND + dd + nt * 8]) =
                make_float2(bcc[nt][0], bcc[nt][1]);
            *reinterpret_cast<float2*>(&g_psum[base + (size_t)kb2 * ND + dd + nt * 8]) =
                make_float2(bcc[nt][2], bcc[nt][3]);
        }
    }
}

// ------- stage 2: reduce chunks, subtract, global norm, scale (fused) -------
__global__ void nv_stage2(const float* __restrict__ cent, float* __restrict__ out) {
    const int g  = blockIdx.x * 128 + threadIdx.x;   // 65536 float4 slots
    const int bk = g >> 5;
    const int b  = bk >> 6;
    const int k  = bk & 63;
    const int d4 = (g & 31) << 2;

    float4 v = make_float4(0.f, 0.f, 0.f, 0.f);
    #pragma unroll
    for (int ch = 0; ch < CHUNKS; ch++) {
        float4 p = *reinterpret_cast<const float4*>(
            &g_psum[(((size_t)(b * CHUNKS + ch) * NK + k) << 7) + d4]);
        v.x += p.x; v.y += p.y; v.z += p.z; v.w += p.w;
    }
    float ss = 0.f;
    #pragma unroll
    for (int ch = 0; ch < CHUNKS; ch++)
        ss += g_ssum[(b * CHUNKS + ch) * NK + k];

    float4 c = *reinterpret_cast<const float4*>(&cent[(((size_t)b * NK + k) << 7) + d4]);
    float4 o;
    o.x = v.x - ss * c.x; o.y = v.y - ss * c.y;
    o.z = v.z - ss * c.z; o.w = v.w - ss * c.w;

    // block-reduce squared sum
    float sq = o.x * o.x + o.y * o.y + o.z * o.z + o.w * o.w;
    #pragma unroll
    for (int off = 16; off; off >>= 1) sq += __shfl_xor_sync(0xffffffffu, sq, off);
    __shared__ float red[4];
    __shared__ float s_scale;
    if ((threadIdx.x & 31) == 0) red[threadIdx.x >> 5] = sq;
    __syncthreads();

    if (threadIdx.x == 0) {
        // writer side (release): sq add, fence, cnt add — all L2 atomics
        atomicAdd(&g_sq, red[0] + red[1] + red[2] + red[3]);
        __threadfence();
        atomicAdd(&g_cnt, 1u);
        // software grid barrier: spin with a morally-strong ACQUIRE load
        // (previous .cg load was weak — no happens-before, caused the 1.5e-3 bug)
        unsigned cnum;
        do {
            asm volatile("ld.acquire.gpu.global.u32 %0, [%1];" : "=r"(cnum) : "l"(&g_cnt));
        } while (cnum < NBLK2);
        __threadfence();
        // atomic RMW read: serialized at LTS after all prior adds that reached L2;
        // cnt==NBLK2 + per-writer fences guarantee every sq-add already has.
        float tot = atomicAdd(&g_sq, 0.0f);
        s_scale = rsqrtf(fmaxf(tot, 1e-12f));
    }
    __syncthreads();

    const float sc = s_scale;
    o.x *= sc; o.y *= sc; o.z *= sc; o.w *= sc;
    *reinterpret_cast<float4*>(&out[(((size_t)b * NK + k) << 7) + d4]) = o;
}

// ---------------- launch ----------------------------------------------------
extern "C" void kernel_launch(void* const* d_in, const int* in_sizes, int n_in,
                              void* d_out, int out_size) {
    const float* feat = (const float*)d_in[0];   // (32,32,32,128) fp32
    const float* cent = (const float*)d_in[1];   // (32,64,128)    fp32
    float* out = (float*)d_out;                  // (32, 8192)     fp32

    cudaFuncSetAttribute(nv_stage1, cudaFuncAttributeMaxDynamicSharedMemorySize, SMEM_TOTAL);

    nv_stage1<<<dim3(CHUNKS, NB), 256, SMEM_TOTAL>>>(feat, cent);
    nv_stage2<<<NBLK2, 128>>>(cent, out);
}

// round 14
// speedup vs baseline: 1.0704x; 1.0704x over previous
#include <cuda_runtime.h>
#include <cuda_bf16.h>
#include <cstdint>

#define NB 32
#define IJ 1024
#define ND 128
#define NK 64
#define CHUNKS 8
#define ROWS 128

#define FSTRB 272      // byte stride, f/c bf16 tiles (136 bf16, conflict-free)
#define SSTRB 144      // byte stride, sim bf16 tiles (72 bf16)

// smem layout (bytes)
#define OFF_FHI 0
#define OFF_FLO 34816
#define OFF_CHI 69632                 // c tiles; sim aliases this region after phase A
#define OFF_CLO 87040
#define OFF_SHI 69632                 // sim hi [128][72] bf16
#define OFF_SLO 88064
#define OFF_F2  106496
#define OFF_C2  107008
#define SMEM_TOTAL 107264

// ---------------- scratch ----------------
__device__ float g_psum[NB * CHUNKS * NK * ND];   // 8 MB
__device__ float g_ssum[NB * CHUNKS * NK];
__device__ float g_sq;

// ---------------- helpers ----------------
__device__ __forceinline__ uint32_t smem_u32(const void* p) {
    uint32_t a;
    asm("{ .reg .u64 t; cvta.to.shared.u64 t, %1; cvt.u32.u64 %0, t; }" : "=r"(a) : "l"(p));
    return a;
}
__device__ __forceinline__ unsigned pack_bf2(float a, float b) {
    __nv_bfloat16 ha = __float2bfloat16(a), hb = __float2bfloat16(b);
    unsigned short ua = *reinterpret_cast<unsigned short*>(&ha);
    unsigned short ub = *reinterpret_cast<unsigned short*>(&hb);
    return (unsigned)ua | ((unsigned)ub << 16);
}
__device__ __forceinline__ void split2(float a, float b, uint32_t& hi, uint32_t& lo) {
    __nv_bfloat16 ha = __float2bfloat16(a), hb = __float2bfloat16(b);
    float fa = __bfloat162float(ha), fb = __bfloat162float(hb);
    hi = pack_bf2(a, b);
    lo = pack_bf2(a - fa, b - fb);
}
__device__ __forceinline__ void ldsm_x4(uint32_t* r, uint32_t addr) {
    asm volatile("ldmatrix.sync.aligned.m8n8.x4.shared.b16 {%0,%1,%2,%3}, [%4];"
                 : "=r"(r[0]), "=r"(r[1]), "=r"(r[2]), "=r"(r[3]) : "r"(addr));
}
__device__ __forceinline__ void ldsm_x4_t(uint32_t* r, uint32_t addr) {
    asm volatile("ldmatrix.sync.aligned.m8n8.x4.trans.shared.b16 {%0,%1,%2,%3}, [%4];"
                 : "=r"(r[0]), "=r"(r[1]), "=r"(r[2]), "=r"(r[3]) : "r"(addr));
}
__device__ __forceinline__ void ldsm_x2(uint32_t* r, uint32_t addr) {
    asm volatile("ldmatrix.sync.aligned.m8n8.x2.shared.b16 {%0,%1}, [%2];"
                 : "=r"(r[0]), "=r"(r[1]) : "r"(addr));
}
__device__ __forceinline__ void ldsm_x2_t(uint32_t* r, uint32_t addr) {
    asm volatile("ldmatrix.sync.aligned.m8n8.x2.trans.shared.b16 {%0,%1}, [%2];"
                 : "=r"(r[0]), "=r"(r[1]) : "r"(addr));
}
__device__ __forceinline__ void mma_bf16(float* d, const uint32_t* a, const uint32_t* b) {
    asm volatile("mma.sync.aligned.m16n8k16.row.col.f32.bf16.bf16.f32 "
                 "{%0,%1,%2,%3}, {%4,%5,%6,%7}, {%8,%9}, {%0,%1,%2,%3};"
                 : "+f"(d[0]), "+f"(d[1]), "+f"(d[2]), "+f"(d[3])
                 : "r"(a[0]), "r"(a[1]), "r"(a[2]), "r"(a[3]), "r"(b[0]), "r"(b[1]));
}

// ---------------- stage 1 (identical to R13 — measured ~15.8us) ----------------
__global__ __launch_bounds__(256, 2)
void nv_stage1(const float* __restrict__ feat, const float* __restrict__ cent) {
    extern __shared__ char smem[];
    const uint32_t sb = smem_u32(smem);
    float* f2 = reinterpret_cast<float*>(smem + OFF_F2);
    float* c2 = reinterpret_cast<float*>(smem + OFF_C2);

    const int b     = blockIdx.y;
    const int chunk = blockIdx.x;
    const int tid   = threadIdx.x;
    const int wid   = tid >> 5;
    const int lane  = tid & 31;

    if (blockIdx.x == 0 && blockIdx.y == 0 && tid == 0) g_sq = 0.f;

    const float* cb = cent + (size_t)b * NK * ND;
    const float* fb = feat + (size_t)b * IJ * ND + (size_t)chunk * ROWS * ND;

    // ---- load f: 128 rows; split to bf16 hi/lo; f2 ----
    #pragma unroll
    for (int p = 0; p < 16; p++) {
        int r = wid + 8 * p;
        float4 v = *reinterpret_cast<const float4*>(&fb[r * ND + lane * 4]);
        uint32_t h0, l0, h1, l1;
        split2(v.x, v.y, h0, l0);
        split2(v.z, v.w, h1, l1);
        *reinterpret_cast<uint2*>(smem + OFF_FHI + r * FSTRB + lane * 8) = make_uint2(h0, h1);
        *reinterpret_cast<uint2*>(smem + OFF_FLO + r * FSTRB + lane * 8) = make_uint2(l0, l1);
        float s = v.x * v.x + v.y * v.y + v.z * v.z + v.w * v.w;
        #pragma unroll
        for (int o = 16; o; o >>= 1) s += __shfl_xor_sync(0xffffffffu, s, o);
        if (lane == 0) f2[r] = s;
    }
    // ---- load c: 64 rows ----
    #pragma unroll
    for (int p = 0; p < 8; p++) {
        int k = wid + 8 * p;
        float4 v = *reinterpret_cast<const float4*>(&cb[k * ND + lane * 4]);
        uint32_t h0, l0, h1, l1;
        split2(v.x, v.y, h0, l0);
        split2(v.z, v.w, h1, l1);
        *reinterpret_cast<uint2*>(smem + OFF_CHI + k * FSTRB + lane * 8) = make_uint2(h0, h1);
        *reinterpret_cast<uint2*>(smem + OFF_CLO + k * FSTRB + lane * 8) = make_uint2(l0, l1);
        float s = v.x * v.x + v.y * v.y + v.z * v.z + v.w * v.w;
        #pragma unroll
        for (int o = 16; o; o >>= 1) s += __shfl_xor_sync(0xffffffffu, s, o);
        if (lane == 0) c2[k] = s;
    }
    __syncthreads();

    // ================= phase A: fc = f . c^T  (HMMA bf16x3) =================
    const int r0 = wid * 16;
    float acc[8][4];
    #pragma unroll
    for (int nt = 0; nt < 8; nt++)
        #pragma unroll
        for (int j = 0; j < 4; j++) acc[nt][j] = 0.f;

    {
        uint32_t a_row = (uint32_t)(r0 + ((lane >> 3) & 1) * 8 + (lane & 7));
        uint32_t a_off = a_row * FSTRB + ((uint32_t)(lane >> 4)) * 16;
        uint32_t ah_addr = sb + OFF_FHI + a_off;
        uint32_t al_addr = sb + OFF_FLO + a_off;
        int l = lane & 15;
        uint32_t b_off0 = (uint32_t)(l & 7) * FSTRB + ((uint32_t)(l >> 3)) * 16;

        #pragma unroll
        for (int kk = 0; kk < 8; kk++) {
            uint32_t ko = kk * 32;             // 16 bf16 = 32 bytes
            uint32_t ah[4], al[4];
            ldsm_x4(ah, ah_addr + ko);
            ldsm_x4(al, al_addr + ko);
            #pragma unroll
            for (int nt = 0; nt < 8; nt++) {
                uint32_t bo = sb + OFF_CHI + b_off0 + (uint32_t)(nt * 8) * FSTRB + ko;
                uint32_t bh[2], bl[2];
                ldsm_x2(bh, bo);
                ldsm_x2(bl, bo + (OFF_CLO - OFF_CHI));
                mma_bf16(acc[nt], ah, bh);
                mma_bf16(acc[nt], ah, bl);
                mma_bf16(acc[nt], al, bh);
            }
        }
    }
    __syncthreads();   // all warps done reading c tiles; sim may alias them

    // ================= softmax (row in a 4-lane group) =================
    {
        const int q  = lane & 3;
        const int ra = r0 + (lane >> 2);
        const int rb = ra + 8;
        const float f2a = f2[ra], f2b = f2[rb];

        float mxa = -1e30f, mxb = -1e30f;
        #pragma unroll
        for (int nt = 0; nt < 8; nt++) {
            float c2x = c2[nt * 8 + 2 * q];
            float c2y = c2[nt * 8 + 2 * q + 1];
            acc[nt][0] = 2.f * acc[nt][0] - f2a - c2x;
            acc[nt][1] = 2.f * acc[nt][1] - f2a - c2y;
            acc[nt][2] = 2.f * acc[nt][2] - f2b - c2x;
            acc[nt][3] = 2.f * acc[nt][3] - f2b - c2y;
            mxa = fmaxf(mxa, fmaxf(acc[nt][0], acc[nt][1]));
            mxb = fmaxf(mxb, fmaxf(acc[nt][2], acc[nt][3]));
        }
        #pragma unroll
        for (int o = 1; o <= 2; o <<= 1) {
            mxa = fmaxf(mxa, __shfl_xor_sync(0xffffffffu, mxa, o));
            mxb = fmaxf(mxb, __shfl_xor_sync(0xffffffffu, mxb, o));
        }
        float sa = 0.f, sbm = 0.f;
        #pragma unroll
        for (int nt = 0; nt < 8; nt++) {
            acc[nt][0] = __expf(acc[nt][0] - mxa);
            acc[nt][1] = __expf(acc[nt][1] - mxa);
            acc[nt][2] = __expf(acc[nt][2] - mxb);
            acc[nt][3] = __expf(acc[nt][3] - mxb);
            sa  += acc[nt][0] + acc[nt][1];
            sbm += acc[nt][2] + acc[nt][3];
        }
        #pragma unroll
        for (int o = 1; o <= 2; o <<= 1) {
            sa  += __shfl_xor_sync(0xffffffffu, sa, o);
            sbm += __shfl_xor_sync(0xffffffffu, sbm, o);
        }
        const float inva = 1.f / sa, invb = 1.f / sbm;

        #pragma unroll
        for (int nt = 0; nt < 8; nt++) {
            float s0 = acc[nt][0] * inva, s1 = acc[nt][1] * inva;
            float s2 = acc[nt][2] * invb, s3 = acc[nt][3] * invb;
            uint32_t h0, l0, h1, l1;
            split2(s0, s1, h0, l0);
            split2(s2, s3, h1, l1);
            uint32_t co = (uint32_t)(nt * 16 + q * 4);
            *reinterpret_cast<uint32_t*>(smem + OFF_SHI + ra * SSTRB + co) = h0;
            *reinterpret_cast<uint32_t*>(smem + OFF_SLO + ra * SSTRB + co) = l0;
            *reinterpret_cast<uint32_t*>(smem + OFF_SHI + rb * SSTRB + co) = h1;
            *reinterpret_cast<uint32_t*>(smem + OFF_SLO + rb * SSTRB + co) = l1;
        }
    }
    __syncthreads();

    // ---- ssum[k] = sum_r (sim_hi + sim_lo)  (threads 0..63, smem column sums) ----
    if (tid < 64) {
        const uint16_t* ph = reinterpret_cast<const uint16_t*>(smem + OFF_SHI) + tid;
        const uint16_t* pl = reinterpret_cast<const uint16_t*>(smem + OFF_SLO) + tid;
        float s = 0.f;
        #pragma unroll 8
        for (int r = 0; r < ROWS; r++) {
            s += __uint_as_float((uint32_t)ph[r * (SSTRB / 2)] << 16);
            s += __uint_as_float((uint32_t)pl[r * (SSTRB / 2)] << 16);
        }
        g_ssum[(b * CHUNKS + chunk) * NK + tid] = s;
    }

    // ================= phase B: psum = sim^T . f  (HMMA bf16x3) =================
    {
        const int mt = wid & 3;          // k-tile (16 k)
        const int dh = wid >> 2;         // d-half (64 d)
        float bcc[8][4];
        #pragma unroll
        for (int nt = 0; nt < 8; nt++)
            #pragma unroll
            for (int j = 0; j < 4; j++) bcc[nt][j] = 0.f;

        uint32_t mi = (uint32_t)(lane >> 3);
        uint32_t sa_off = ((mi >> 1) * 8 + (uint32_t)(lane & 7)) * SSTRB
                        + ((uint32_t)(mt * 16) + (mi & 1) * 8) * 2;
        uint32_t fb_row = (((uint32_t)(lane & 15) >> 3) * 8 + (uint32_t)(lane & 7));

        #pragma unroll
        for (int rr = 0; rr < 8; rr++) {
            uint32_t sh[4], sl[4];
            uint32_t sa_addr = sb + OFF_SHI + (uint32_t)(rr * 16) * SSTRB + sa_off;
            ldsm_x4_t(sh, sa_addr);
            ldsm_x4_t(sl, sa_addr + (OFF_SLO - OFF_SHI));
            uint32_t fbase = (uint32_t)(rr * 16) * FSTRB + fb_row * FSTRB;
            #pragma unroll
            for (int nt = 0; nt < 8; nt++) {
                uint32_t n0 = (uint32_t)(dh * 64 + nt * 8);
                uint32_t fh[2], fl[2];
                ldsm_x2_t(fh, sb + OFF_FHI + fbase + n0 * 2);
                ldsm_x2_t(fl, sb + OFF_FLO + fbase + n0 * 2);
                mma_bf16(bcc[nt], sh, fh);
                mma_bf16(bcc[nt], sh, fl);
                mma_bf16(bcc[nt], sl, fh);
            }
        }

        // epilogue: write fragments to g_psum
        const size_t base = ((size_t)(b * CHUNKS + chunk) * NK) * ND;
        const int ka  = mt * 16 + (lane >> 2);
        const int kb2 = ka + 8;
        const int dd  = dh * 64 + 2 * (lane & 3);
        #pragma unroll
        for (int nt = 0; nt < 8; nt++) {
            *reinterpret_cast<float2*>(&g_psum[base + (size_t)ka * ND + dd + nt * 8]) =
                make_float2(bcc[nt][0], bcc[nt][1]);
            *reinterpret_cast<float2*>(&g_psum[base + (size_t)kb2 * ND + dd + nt * 8]) =
                make_float2(bcc[nt][2], bcc[nt][3]);
        }
    }
}

// ---------------- stage 2: reduce chunks, subtract, atomic sq-sum ---------
__global__ void nv_stage2(const float* __restrict__ cent, float* __restrict__ out) {
    const int g  = blockIdx.x * 128 + threadIdx.x;   // 65536 float4 slots
    const int bk = g >> 5;
    const int b  = bk >> 6;
    const int k  = bk & 63;
    const int d4 = (g & 31) << 2;

    float4 v = make_float4(0.f, 0.f, 0.f, 0.f);
    #pragma unroll
    for (int ch = 0; ch < CHUNKS; ch++) {
        float4 p = *reinterpret_cast<const float4*>(
            &g_psum[(((size_t)(b * CHUNKS + ch) * NK + k) << 7) + d4]);
        v.x += p.x; v.y += p.y; v.z += p.z; v.w += p.w;
    }
    float ss = 0.f;
    #pragma unroll
    for (int ch = 0; ch < CHUNKS; ch++)
        ss += g_ssum[(b * CHUNKS + ch) * NK + k];

    float4 c = *reinterpret_cast<const float4*>(&cent[(((size_t)b * NK + k) << 7) + d4]);
    float4 o;
    o.x = v.x - ss * c.x; o.y = v.y - ss * c.y;
    o.z = v.z - ss * c.z; o.w = v.w - ss * c.w;
    *reinterpret_cast<float4*>(&out[(((size_t)b * NK + k) << 7) + d4]) = o;

    float sq = o.x * o.x + o.y * o.y + o.z * o.z + o.w * o.w;
    #pragma unroll
    for (int off = 16; off; off >>= 1) sq += __shfl_xor_sync(0xffffffffu, sq, off);
    __shared__ float red[4];
    if ((threadIdx.x & 31) == 0) red[threadIdx.x >> 5] = sq;
    __syncthreads();
    if (threadIdx.x == 0)
        atomicAdd(&g_sq, red[0] + red[1] + red[2] + red[3]);
}

// ---------------- stage 4: apply global scale (kernel boundary = sync) ------
__global__ void nv_stage4(float* __restrict__ out) {
    const int i = blockIdx.x * blockDim.x + threadIdx.x;   // 65536 float4
    const float sc = rsqrtf(fmaxf(g_sq, 1e-12f));
    float4* o4 = reinterpret_cast<float4*>(out);
    float4 v = o4[i];
    v.x *= sc; v.y *= sc; v.z *= sc; v.w *= sc;
    o4[i] = v;
}

// ---------------- launch ----------------------------------------------------
extern "C" void kernel_launch(void* const* d_in, const int* in_sizes, int n_in,
                              void* d_out, int out_size) {
    const float* feat = (const float*)d_in[0];   // (32,32,32,128) fp32
    const float* cent = (const float*)d_in[1];   // (32,64,128)    fp32
    float* out = (float*)d_out;                  // (32, 8192)     fp32

    cudaFuncSetAttribute(nv_stage1, cudaFuncAttributeMaxDynamicSharedMemorySize, SMEM_TOTAL);

    nv_stage1<<<dim3(CHUNKS, NB), 256, SMEM_TOTAL>>>(feat, cent);
    nv_stage2<<<512, 128>>>(cent, out);
    nv_stage4<<<256, 256>>>(out);
}

// round 16
// speedup vs baseline: 1.0880x; 1.0165x over previous
#include <cuda_runtime.h>
#include <cuda_bf16.h>
#include <cstdint>

#define NB 32
#define IJ 1024
#define ND 128
#define NK 64
#define CHUNKS 8
#define ROWS 128

#define FSTRB 272      // byte stride, f/c bf16 tiles (136 bf16, conflict-free)
#define SSTRB 144      // byte stride, sim bf16 tiles (72 bf16)

// smem layout (bytes)
#define OFF_FHI 0
#define OFF_FLO 34816
#define OFF_CHI 69632                 // c tiles; sim aliases this region after phase A
#define OFF_CLO 87040
#define OFF_SHI 69632                 // sim hi [128][72] bf16
#define OFF_SLO 88064
#define OFF_F2  106496
#define OFF_C2  107008
#define SMEM_TOTAL 107264

// ---------------- scratch ----------------
__device__ float g_psum[NB * CHUNKS * NK * ND];   // 8 MB
__device__ float g_ssum[NB * CHUNKS * NK];
__device__ float g_sq;

// ---------------- helpers ----------------
__device__ __forceinline__ uint32_t smem_u32(const void* p) {
    uint32_t a;
    asm("{ .reg .u64 t; cvta.to.shared.u64 t, %1; cvt.u32.u64 %0, t; }" : "=r"(a) : "l"(p));
    return a;
}
__device__ __forceinline__ unsigned pack_bf2(float a, float b) {
    __nv_bfloat16 ha = __float2bfloat16(a), hb = __float2bfloat16(b);
    unsigned short ua = *reinterpret_cast<unsigned short*>(&ha);
    unsigned short ub = *reinterpret_cast<unsigned short*>(&hb);
    return (unsigned)ua | ((unsigned)ub << 16);
}
__device__ __forceinline__ void split2(float a, float b, uint32_t& hi, uint32_t& lo) {
    __nv_bfloat16 ha = __float2bfloat16(a), hb = __float2bfloat16(b);
    float fa = __bfloat162float(ha), fb = __bfloat162float(hb);
    hi = pack_bf2(a, b);
    lo = pack_bf2(a - fa, b - fb);
}
__device__ __forceinline__ void ldsm_x4(uint32_t* r, uint32_t addr) {
    asm volatile("ldmatrix.sync.aligned.m8n8.x4.shared.b16 {%0,%1,%2,%3}, [%4];"
                 : "=r"(r[0]), "=r"(r[1]), "=r"(r[2]), "=r"(r[3]) : "r"(addr));
}
__device__ __forceinline__ void ldsm_x4_t(uint32_t* r, uint32_t addr) {
    asm volatile("ldmatrix.sync.aligned.m8n8.x4.trans.shared.b16 {%0,%1,%2,%3}, [%4];"
                 : "=r"(r[0]), "=r"(r[1]), "=r"(r[2]), "=r"(r[3]) : "r"(addr));
}
__device__ __forceinline__ void ldsm_x2(uint32_t* r, uint32_t addr) {
    asm volatile("ldmatrix.sync.aligned.m8n8.x2.shared.b16 {%0,%1}, [%2];"
                 : "=r"(r[0]), "=r"(r[1]) : "r"(addr));
}
__device__ __forceinline__ void ldsm_x2_t(uint32_t* r, uint32_t addr) {
    asm volatile("ldmatrix.sync.aligned.m8n8.x2.trans.shared.b16 {%0,%1}, [%2];"
                 : "=r"(r[0]), "=r"(r[1]) : "r"(addr));
}
__device__ __forceinline__ void mma_bf16(float* d, const uint32_t* a, const uint32_t* b) {
    asm volatile("mma.sync.aligned.m16n8k16.row.col.f32.bf16.bf16.f32 "
                 "{%0,%1,%2,%3}, {%4,%5,%6,%7}, {%8,%9}, {%0,%1,%2,%3};"
                 : "+f"(d[0]), "+f"(d[1]), "+f"(d[2]), "+f"(d[3])
                 : "r"(a[0]), "r"(a[1]), "r"(a[2]), "r"(a[3]), "r"(b[0]), "r"(b[1]));
}

// ---------------- stage 1 ----------------
__global__ __launch_bounds__(256, 2)
void nv_stage1(const float* __restrict__ feat, const float* __restrict__ cent) {
    extern __shared__ char smem[];
    const uint32_t sb = smem_u32(smem);
    float* f2 = reinterpret_cast<float*>(smem + OFF_F2);
    float* c2 = reinterpret_cast<float*>(smem + OFF_C2);

    const int b     = blockIdx.y;
    const int chunk = blockIdx.x;
    const int tid   = threadIdx.x;
    const int wid   = tid >> 5;
    const int lane  = tid & 31;

    if (blockIdx.x == 0 && blockIdx.y == 0 && tid == 0) g_sq = 0.f;

    const float* cb = cent + (size_t)b * NK * ND;
    const float* fb = feat + (size_t)b * IJ * ND + (size_t)chunk * ROWS * ND;

    // ---- load f: 128 rows; split to bf16 hi/lo; f2 ----
    #pragma unroll
    for (int p = 0; p < 16; p++) {
        int r = wid + 8 * p;
        float4 v = *reinterpret_cast<const float4*>(&fb[r * ND + lane * 4]);
        uint32_t h0, l0, h1, l1;
        split2(v.x, v.y, h0, l0);
        split2(v.z, v.w, h1, l1);
        *reinterpret_cast<uint2*>(smem + OFF_FHI + r * FSTRB + lane * 8) = make_uint2(h0, h1);
        *reinterpret_cast<uint2*>(smem + OFF_FLO + r * FSTRB + lane * 8) = make_uint2(l0, l1);
        float s = v.x * v.x + v.y * v.y + v.z * v.z + v.w * v.w;
        #pragma unroll
        for (int o = 16; o; o >>= 1) s += __shfl_xor_sync(0xffffffffu, s, o);
        if (lane == 0) f2[r] = s;
    }
    // ---- load c: 64 rows ----
    #pragma unroll
    for (int p = 0; p < 8; p++) {
        int k = wid + 8 * p;
        float4 v = *reinterpret_cast<const float4*>(&cb[k * ND + lane * 4]);
        uint32_t h0, l0, h1, l1;
        split2(v.x, v.y, h0, l0);
        split2(v.z, v.w, h1, l1);
        *reinterpret_cast<uint2*>(smem + OFF_CHI + k * FSTRB + lane * 8) = make_uint2(h0, h1);
        *reinterpret_cast<uint2*>(smem + OFF_CLO + k * FSTRB + lane * 8) = make_uint2(l0, l1);
        float s = v.x * v.x + v.y * v.y + v.z * v.z + v.w * v.w;
        #pragma unroll
        for (int o = 16; o; o >>= 1) s += __shfl_xor_sync(0xffffffffu, s, o);
        if (lane == 0) c2[k] = s;
    }
    __syncthreads();

    // ================= phase A: fc = f . c^T  (HMMA bf16x3, pipelined) ======
    const int r0 = wid * 16;
    float acc[8][4];
    #pragma unroll
    for (int nt = 0; nt < 8; nt++)
        #pragma unroll
        for (int j = 0; j < 4; j++) acc[nt][j] = 0.f;

    {
        uint32_t a_row = (uint32_t)(r0 + ((lane >> 3) & 1) * 8 + (lane & 7));
        uint32_t a_off = a_row * FSTRB + ((uint32_t)(lane >> 4)) * 16;
        uint32_t ah_addr = sb + OFF_FHI + a_off;
        uint32_t al_addr = sb + OFF_FLO + a_off;
        int l = lane & 15;
        uint32_t bbase = sb + OFF_CHI + (uint32_t)(l & 7) * FSTRB + ((uint32_t)(l >> 3)) * 16;

        // double buffers
        uint32_t ah[2][4], al[2][4];
        uint32_t bh[2][2], bl[2][2];

        // preload kk=0 A and (kk=0, nt=0) B
        ldsm_x4(ah[0], ah_addr);
        ldsm_x4(al[0], al_addr);
        ldsm_x2(bh[0], bbase);
        ldsm_x2(bl[0], bbase + (OFF_CLO - OFF_CHI));

        #pragma unroll
        for (int kk = 0; kk < 8; kk++) {
            const int ab = kk & 1;
            // prefetch next kk's A fragments early
            if (kk < 7) {
                ldsm_x4(ah[ab ^ 1], ah_addr + (uint32_t)((kk + 1) * 32));
                ldsm_x4(al[ab ^ 1], al_addr + (uint32_t)((kk + 1) * 32));
            }
            #pragma unroll
            for (int nt = 0; nt < 8; nt++) {
                const int cur = nt & 1;
                const int nxt = cur ^ 1;
                // prefetch next B fragment pair (next nt, or nt=0 of next kk)
                if (nt < 7) {
                    uint32_t bo = bbase + (uint32_t)((nt + 1) * 8) * FSTRB + (uint32_t)(kk * 32);
                    ldsm_x2(bh[nxt], bo);
                    ldsm_x2(bl[nxt], bo + (OFF_CLO - OFF_CHI));
                } else if (kk < 7) {
                    uint32_t bo = bbase + (uint32_t)((kk + 1) * 32);
                    ldsm_x2(bh[nxt], bo);
                    ldsm_x2(bl[nxt], bo + (OFF_CLO - OFF_CHI));
                }
                mma_bf16(acc[nt], ah[ab], bh[cur]);
                mma_bf16(acc[nt], ah[ab], bl[cur]);
                mma_bf16(acc[nt], al[ab], bh[cur]);
            }
        }
    }
    __syncthreads();   // all warps done reading c tiles; sim may alias them

    // ================= softmax (row in a 4-lane group) =================
    {
        const int q  = lane & 3;
        const int ra = r0 + (lane >> 2);
        const int rb = ra + 8;
        const float f2a = f2[ra], f2b = f2[rb];

        float mxa = -1e30f, mxb = -1e30f;
        #pragma unroll
        for (int nt = 0; nt < 8; nt++) {
            float c2x = c2[nt * 8 + 2 * q];
            float c2y = c2[nt * 8 + 2 * q + 1];
            acc[nt][0] = 2.f * acc[nt][0] - f2a - c2x;
            acc[nt][1] = 2.f * acc[nt][1] - f2a - c2y;
            acc[nt][2] = 2.f * acc[nt][2] - f2b - c2x;
            acc[nt][3] = 2.f * acc[nt][3] - f2b - c2y;
            mxa = fmaxf(mxa, fmaxf(acc[nt][0], acc[nt][1]));
            mxb = fmaxf(mxb, fmaxf(acc[nt][2], acc[nt][3]));
        }
        #pragma unroll
        for (int o = 1; o <= 2; o <<= 1) {
            mxa = fmaxf(mxa, __shfl_xor_sync(0xffffffffu, mxa, o));
            mxb = fmaxf(mxb, __shfl_xor_sync(0xffffffffu, mxb, o));
        }
        float sa = 0.f, sbm = 0.f;
        #pragma unroll
        for (int nt = 0; nt < 8; nt++) {
            acc[nt][0] = __expf(acc[nt][0] - mxa);
            acc[nt][1] = __expf(acc[nt][1] - mxa);
            acc[nt][2] = __expf(acc[nt][2] - mxb);
            acc[nt][3] = __expf(acc[nt][3] - mxb);
            sa  += acc[nt][0] + acc[nt][1];
            sbm += acc[nt][2] + acc[nt][3];
        }
        #pragma unroll
        for (int o = 1; o <= 2; o <<= 1) {
            sa  += __shfl_xor_sync(0xffffffffu, sa, o);
            sbm += __shfl_xor_sync(0xffffffffu, sbm, o);
        }
        const float inva = 1.f / sa, invb = 1.f / sbm;

        #pragma unroll
        for (int nt = 0; nt < 8; nt++) {
            float s0 = acc[nt][0] * inva, s1 = acc[nt][1] * inva;
            float s2 = acc[nt][2] * invb, s3 = acc[nt][3] * invb;
            uint32_t h0, l0, h1, l1;
            split2(s0, s1, h0, l0);
            split2(s2, s3, h1, l1);
            uint32_t co = (uint32_t)(nt * 16 + q * 4);
            *reinterpret_cast<uint32_t*>(smem + OFF_SHI + ra * SSTRB + co) = h0;
            *reinterpret_cast<uint32_t*>(smem + OFF_SLO + ra * SSTRB + co) = l0;
            *reinterpret_cast<uint32_t*>(smem + OFF_SHI + rb * SSTRB + co) = h1;
            *reinterpret_cast<uint32_t*>(smem + OFF_SLO + rb * SSTRB + co) = l1;
        }
    }
    __syncthreads();

    // ---- ssum[k] = sum_r (sim_hi + sim_lo)  (threads 0..63, smem column sums) ----
    if (tid < 64) {
        const uint16_t* ph = reinterpret_cast<const uint16_t*>(smem + OFF_SHI) + tid;
        const uint16_t* pl = reinterpret_cast<const uint16_t*>(smem + OFF_SLO) + tid;
        float s = 0.f;
        #pragma unroll 8
        for (int r = 0; r < ROWS; r++) {
            s += __uint_as_float((uint32_t)ph[r * (SSTRB / 2)] << 16);
            s += __uint_as_float((uint32_t)pl[r * (SSTRB / 2)] << 16);
        }
        g_ssum[(b * CHUNKS + chunk) * NK + tid] = s;
    }

    // ================= phase B: psum = sim^T . f  (HMMA bf16x3, pipelined) ==
    {
        const int mt = wid & 3;          // k-tile (16 k)
        const int dh = wid >> 2;         // d-half (64 d)
        float bcc[8][4];
        #pragma unroll
        for (int nt = 0; nt < 8; nt++)
            #pragma unroll
            for (int j = 0; j < 4; j++) bcc[nt][j] = 0.f;

        uint32_t mi = (uint32_t)(lane >> 3);
        uint32_t sa_off = ((mi >> 1) * 8 + (uint32_t)(lane & 7)) * SSTRB
                        + ((uint32_t)(mt * 16) + (mi & 1) * 8) * 2;
        uint32_t fb_row = (((uint32_t)(lane & 15) >> 3) * 8 + (uint32_t)(lane & 7));
        uint32_t fbase0 = sb + OFF_FHI + fb_row * FSTRB + (uint32_t)(dh * 64) * 2;

        // double buffers
        uint32_t sh[2][4], sl[2][4];
        uint32_t fh[2][2], fl[2][2];

        // preload rr=0 sim-A and (rr=0, nt=0) f-B
        {
            uint32_t sa_addr = sb + OFF_SHI + sa_off;
            ldsm_x4_t(sh[0], sa_addr);
            ldsm_x4_t(sl[0], sa_addr + (OFF_SLO - OFF_SHI));
            ldsm_x2_t(fh[0], fbase0);
            ldsm_x2_t(fl[0], fbase0 + (OFF_FLO - OFF_FHI));
        }

        #pragma unroll
        for (int rr = 0; rr < 8; rr++) {
            const int ab = rr & 1;
            if (rr < 7) {
                uint32_t sa_addr = sb + OFF_SHI + (uint32_t)((rr + 1) * 16) * SSTRB + sa_off;
                ldsm_x4_t(sh[ab ^ 1], sa_addr);
                ldsm_x4_t(sl[ab ^ 1], sa_addr + (OFF_SLO - OFF_SHI));
            }
            #pragma unroll
            for (int nt = 0; nt < 8; nt++) {
                const int cur = nt & 1;
                const int nxt = cur ^ 1;
                if (nt < 7) {
                    uint32_t fo = fbase0 + (uint32_t)(rr * 16) * FSTRB + (uint32_t)((nt + 1) * 8) * 2;
                    ldsm_x2_t(fh[nxt], fo);
                    ldsm_x2_t(fl[nxt], fo + (OFF_FLO - OFF_FHI));
                } else if (rr < 7) {
                    uint32_t fo = fbase0 + (uint32_t)((rr + 1) * 16) * FSTRB;
                    ldsm_x2_t(fh[nxt], fo);
                    ldsm_x2_t(fl[nxt], fo + (OFF_FLO - OFF_FHI));
                }
                mma_bf16(bcc[nt], sh[ab], fh[cur]);
                mma_bf16(bcc[nt], sh[ab], fl[cur]);
                mma_bf16(bcc[nt], sl[ab], fh[cur]);
            }
        }

        // epilogue: write fragments to g_psum
        const size_t base = ((size_t)(b * CHUNKS + chunk) * NK) * ND;
        const int ka  = mt * 16 + (lane >> 2);
        const int kb2 = ka + 8;
        const int dd  = dh * 64 + 2 * (lane & 3);
        #pragma unroll
        for (int nt = 0; nt < 8; nt++) {
            *reinterpret_cast<float2*>(&g_psum[base + (size_t)ka * ND + dd + nt * 8]) =
                make_float2(bcc[nt][0], bcc[nt][1]);
            *reinterpret_cast<float2*>(&g_psum[base + (size_t)kb2 * ND + dd + nt * 8]) =
                make_float2(bcc[nt][2], bcc[nt][3]);
        }
    }
}

// ---------------- stage 2: reduce chunks, subtract, atomic sq-sum ---------
__global__ void nv_stage2(const float* __restrict__ cent, float* __restrict__ out) {
    const int g  = blockIdx.x * 128 + threadIdx.x;   // 65536 float4 slots
    const int bk = g >> 5;
    const int b  = bk >> 6;
    const int k  = bk & 63;
    const int d4 = (g & 31) << 2;

    float4 v = make_float4(0.f, 0.f, 0.f, 0.f);
    #pragma unroll
    for (int ch = 0; ch < CHUNKS; ch++) {
        float4 p = *reinterpret_cast<const float4*>(
            &g_psum[(((size_t)(b * CHUNKS + ch) * NK + k) << 7) + d4]);
        v.x += p.x; v.y += p.y; v.z += p.z; v.w += p.w;
    }
    float ss = 0.f;
    #pragma unroll
    for (int ch = 0; ch < CHUNKS; ch++)
        ss += g_ssum[(b * CHUNKS + ch) * NK + k];

    float4 c = *reinterpret_cast<const float4*>(&cent[(((size_t)b * NK + k) << 7) + d4]);
    float4 o;
    o.x = v.x - ss * c.x; o.y = v.y - ss * c.y;
    o.z = v.z - ss * c.z; o.w = v.w - ss * c.w;
    *reinterpret_cast<float4*>(&out[(((size_t)b * NK + k) << 7) + d4]) = o;

    float sq = o.x * o.x + o.y * o.y + o.z * o.z + o.w * o.w;
    #pragma unroll
    for (int off = 16; off; off >>= 1) sq += __shfl_xor_sync(0xffffffffu, sq, off);
    __shared__ float red[4];
    if ((threadIdx.x & 31) == 0) red[threadIdx.x >> 5] = sq;
    __syncthreads();
    if (threadIdx.x == 0)
        atomicAdd(&g_sq, red[0] + red[1] + red[2] + red[3]);
}

// ---------------- stage 4: apply global scale (kernel boundary = sync) ------
__global__ void nv_stage4(float* __restrict__ out) {
    const int i = blockIdx.x * blockDim.x + threadIdx.x;   // 65536 float4
    const float sc = rsqrtf(fmaxf(g_sq, 1e-12f));
    float4* o4 = reinterpret_cast<float4*>(out);
    float4 v = o4[i];
    v.x *= sc; v.y *= sc; v.z *= sc; v.w *= sc;
    o4[i] = v;
}

// ---------------- launch ----------------------------------------------------
extern "C" void kernel_launch(void* const* d_in, const int* in_sizes, int n_in,
                              void* d_out, int out_size) {
    const float* feat = (const float*)d_in[0];   // (32,32,32,128) fp32
    const float* cent = (const float*)d_in[1];   // (32,64,128)    fp32
    float* out = (float*)d_out;                  // (32, 8192)     fp32

    cudaFuncSetAttribute(nv_stage1, cudaFuncAttributeMaxDynamicSharedMemorySize, SMEM_TOTAL);

    nv_stage1<<<dim3(CHUNKS, NB), 256, SMEM_TOTAL>>>(feat, cent);
    nv_stage2<<<512, 128>>>(cent, out);
    nv_stage4<<<256, 256>>>(out);
}